// round 12
// baseline (speedup 1.0000x reference)
#include <cuda_runtime.h>
#include <math.h>
#include <stdint.h>

// Problem constants
#define BATCH 8
#define TT    4096
#define DD    768
#define HH    768
#define MM    (BATCH * TT)      // 32768 rows
#define CHUNK 128
#define NC    (TT / CHUNK)      // 32 chunks

#define NKB   (DD / 8)          // 96 k8 blocks
#define NMB   (MM / 16)         // 2048 m16 blocks
#define NNB   (HH / 8)          // 96 n8 blocks

// Scratch (static device globals)
__device__ float g_A [(size_t)MM * HH];
__device__ float g_Bv[(size_t)MM * HH];
__device__ float g_Xf[(size_t)MM * DD];        // fragment-major tf32 x
__device__ float g_Wf[(size_t)3 * HH * DD];    // fragment-major tf32 weights
__device__ float g_aggA[BATCH * NC * HH];
__device__ float g_aggB[BATCH * NC * HH];
__device__ float g_pref[BATCH * NC * HH];

// ---------------------------------------------------------------------------
// GEMM: BM=128 x BN=64 x BK=32, 256 threads, 8 warps (2m x 4n), warp tile
// 64x16 = 4(m16) x 2(n8) mma tiles x 3 projections = 24 mma / 10 LDS per kk.
// 4-stage cp.async pipeline on fragment-major operands.
// ---------------------------------------------------------------------------
#define GBM 128
#define GBN 64
#define STAGES 4
#define N_ITERS (DD / 32)            // 24 iterations of 4 k8-blocks
#define A_STG_FLOATS 4096            // 8 m16 x 4 k8 x 128
#define B_STG_FLOATS 2048            // 8 n8  x 4 k8 x 64, per projection
#define STAGE_FLOATS (A_STG_FLOATS + 3 * B_STG_FLOATS)   // 10240 (40 KB)
#define SMEM_BYTES (STAGES * STAGE_FLOATS * 4)           // 163840

__device__ __forceinline__ float tf32r(float f) {
    uint32_t u;
    asm("cvt.rna.tf32.f32 %0, %1;" : "=r"(u) : "f"(f));
    return __uint_as_float(u);
}
__device__ __forceinline__ uint32_t smem_u32(const void* p) {
    uint32_t a;
    asm("{ .reg .u64 t; cvta.to.shared.u64 t, %1; cvt.u32.u64 %0, t; }" : "=r"(a) : "l"(p));
    return a;
}
__device__ __forceinline__ void cp16(uint32_t d, const float* g) {
    uint64_t ga;
    asm("cvta.to.global.u64 %0, %1;" : "=l"(ga) : "l"(g));
    asm volatile("cp.async.cg.shared.global [%0], [%1], 16;" :: "r"(d), "l"(ga) : "memory");
}
__device__ __forceinline__ void mma_tf32(float& c0, float& c1, float& c2, float& c3,
                                         uint32_t a0, uint32_t a1, uint32_t a2, uint32_t a3,
                                         uint32_t b0, uint32_t b1) {
    asm volatile(
        "mma.sync.aligned.m16n8k8.row.col.f32.tf32.tf32.f32 "
        "{%0,%1,%2,%3}, {%4,%5,%6,%7}, {%8,%9}, {%0,%1,%2,%3};\n"
        : "+f"(c0), "+f"(c1), "+f"(c2), "+f"(c3)
        : "r"(a0), "r"(a1), "r"(a2), "r"(a3), "r"(b0), "r"(b1));
}

extern __shared__ float smf[];

__global__ __launch_bounds__(256, 1)
void gates_gemm_fm(const float* __restrict__ fb, const float* __restrict__ ib,
                   const float* __restrict__ hb)
{
    const int tid = threadIdx.x;
    const int L   = tid & 31;
    const int w   = tid >> 5;
    const int wm  = w >> 2;          // 0..1 -> 64-row band
    const int wn  = w & 3;           // 0..3 -> 16-col band
    const int m0b = blockIdx.y * GBM;
    const int n0b = blockIdx.x * GBN;
    const int mb0 = blockIdx.y * 8;  // first m16 block (8 per CTA)
    const int nb0 = blockIdx.x * 8;  // first n8 block

    const uint32_t s_u = smem_u32(smf);

    float cf[4][2][4] = {}, ci[4][2][4] = {}, ch[4][2][4] = {};

    // Stage fill: pure linear copies (fragment-major global layout).
    // A: 8 segments of 2KB (one per m16 block, 4 contiguous k8 blocks).
    // B: per proj, 8 segments of 1KB (one per n8 block).
#define ISSUE_LOAD(ST, IT)                                                     \
    {                                                                          \
        uint32_t sb = s_u + (uint32_t)(ST) * (STAGE_FLOATS * 4);               \
        const int kb0 = (IT) * 4;                                              \
        _Pragma("unroll")                                                      \
        for (int i = 0; i < 4; i++) {                                          \
            int chunk = tid + i * 256;           /* 0..1023, 16B each */       \
            int seg = chunk >> 7, within = chunk & 127;                        \
            const float* gs = g_Xf + (((size_t)(mb0 + seg) * NKB + kb0) * 128) \
                              + within * 4;                                    \
            cp16(sb + chunk * 16, gs);                                         \
        }                                                                      \
        _Pragma("unroll")                                                      \
        for (int p = 0; p < 3; p++) {                                          \
            uint32_t bb = sb + (A_STG_FLOATS + p * B_STG_FLOATS) * 4;          \
            _Pragma("unroll")                                                  \
            for (int i = 0; i < 2; i++) {                                      \
                int chunk = tid + i * 256;       /* 0..511 */                  \
                int seg = chunk >> 6, within = chunk & 63;                     \
                const float* gs = g_Wf +                                       \
                    (((size_t)(p * NNB + nb0 + seg) * NKB + kb0) * 64)         \
                    + within * 4;                                              \
                cp16(bb + chunk * 16, gs);                                     \
            }                                                                  \
        }                                                                      \
    }

#define COMPUTE(ST)                                                            \
    {                                                                          \
        const float* sA  = smf + (ST) * STAGE_FLOATS;                          \
        const float* sB0 = sA + A_STG_FLOATS;                                  \
        const float* sB1 = sB0 + B_STG_FLOATS;                                 \
        const float* sB2 = sB1 + B_STG_FLOATS;                                 \
        _Pragma("unroll")                                                      \
        for (int kb4 = 0; kb4 < 4; kb4++) {                                    \
            uint32_t A[4][4];                                                  \
            _Pragma("unroll")                                                  \
            for (int mt = 0; mt < 4; mt++) {                                   \
                int mb8 = wm * 4 + mt;                                         \
                float4 av = *(const float4*)&sA[(mb8 * 4 + kb4) * 128 + L * 4];\
                A[mt][0] = __float_as_uint(av.x);                              \
                A[mt][1] = __float_as_uint(av.y);                              \
                A[mt][2] = __float_as_uint(av.z);                              \
                A[mt][3] = __float_as_uint(av.w);                              \
            }                                                                  \
            _Pragma("unroll")                                                  \
            for (int nt = 0; nt < 2; nt++) {                                   \
                int off = ((wn * 2 + nt) * 4 + kb4) * 64 + L * 2;              \
                float2 vf = *(const float2*)&sB0[off];                         \
                float2 vi = *(const float2*)&sB1[off];                         \
                float2 vh = *(const float2*)&sB2[off];                         \
                _Pragma("unroll")                                              \
                for (int mt = 0; mt < 4; mt++) {                               \
                    mma_tf32(cf[mt][nt][0], cf[mt][nt][1], cf[mt][nt][2], cf[mt][nt][3], \
                             A[mt][0], A[mt][1], A[mt][2], A[mt][3],           \
                             __float_as_uint(vf.x), __float_as_uint(vf.y));    \
                    mma_tf32(ci[mt][nt][0], ci[mt][nt][1], ci[mt][nt][2], ci[mt][nt][3], \
                             A[mt][0], A[mt][1], A[mt][2], A[mt][3],           \
                             __float_as_uint(vi.x), __float_as_uint(vi.y));    \
                    mma_tf32(ch[mt][nt][0], ch[mt][nt][1], ch[mt][nt][2], ch[mt][nt][3], \
                             A[mt][0], A[mt][1], A[mt][2], A[mt][3],           \
                             __float_as_uint(vh.x), __float_as_uint(vh.y));    \
                }                                                              \
            }                                                                  \
        }                                                                      \
    }

    // ---- prologue: fill STAGES-1 stages ----
    #pragma unroll
    for (int s = 0; s < STAGES - 1; s++) {
        ISSUE_LOAD(s, s);
        asm volatile("cp.async.commit_group;" ::: "memory");
    }

    // ---- mainloop: one sync per iter ----
    for (int it = 0; it < N_ITERS; it++) {
        asm volatile("cp.async.wait_group %0;" :: "n"(STAGES - 2) : "memory");
        __syncthreads();
        int nk = it + STAGES - 1;
        if (nk < N_ITERS) { ISSUE_LOAD(nk & (STAGES - 1), nk); }
        asm volatile("cp.async.commit_group;" ::: "memory");
        COMPUTE(it & (STAGES - 1));
    }

    // ---- epilogue: gates -> (a, b) scan coefficients ----
    #pragma unroll
    for (int mt = 0; mt < 4; mt++) {
        #pragma unroll
        for (int nt = 0; nt < 2; nt++) {
            int rbase = m0b + wm * 64 + mt * 16 + (L >> 2);
            int cbase = n0b + wn * 16 + nt * 8 + 2 * (L & 3);
            #pragma unroll
            for (int e = 0; e < 4; e++) {
                int m = rbase + ((e >> 1) ? 8 : 0);
                int h = cbase + (e & 1);
                float fv = 1.0f / (1.0f + __expf(-(cf[mt][nt][e] + fb[h])));
                float iv = 1.0f / (1.0f + __expf(-(ci[mt][nt][e] + ib[h])));
                float ht = ch[mt][nt][e] + hb[h];
                float inv_den = 1.0f / (fv + iv + 1e-8f);
                size_t o = (size_t)m * HH + h;
                g_A [o] = fv * inv_den;
                g_Bv[o] = iv * inv_den * ht;
            }
        }
    }
#undef ISSUE_LOAD
#undef COMPUTE
}

// ---------------------------------------------------------------------------
// Prep: permute + tf32-round operands into fragment-major scratch.
// ---------------------------------------------------------------------------
__global__ void permute_x_kernel(const float* __restrict__ x)
{
    int idx = blockIdx.x * blockDim.x + threadIdx.x;   // < NMB*NKB*32
    int L  = idx & 31;
    int kb = (idx >> 5) % NKB;
    int mb = (idx >> 5) / NKB;
    int r = mb * 16 + (L >> 2);
    int c = kb * 8 + (L & 3);
    float4 v;
    v.x = tf32r(x[(size_t)r * DD + c]);
    v.y = tf32r(x[(size_t)(r + 8) * DD + c]);
    v.z = tf32r(x[(size_t)r * DD + c + 4]);
    v.w = tf32r(x[(size_t)(r + 8) * DD + c + 4]);
    *(float4*)&g_Xf[(size_t)idx * 4] = v;
}

__global__ void permute_w_kernel(const float* __restrict__ fw,
                                 const float* __restrict__ iw,
                                 const float* __restrict__ hw)
{
    int idx = blockIdx.x * blockDim.x + threadIdx.x;   // < 3*NNB*NKB*32
    int L  = idx & 31;
    int kb = (idx >> 5) % NKB;
    int nb = ((idx >> 5) / NKB) % NNB;
    int p  = (idx >> 5) / (NKB * NNB);
    int n = nb * 8 + (L >> 2);
    int k = kb * 8 + (L & 3);
    const float* W = (p == 0) ? fw : (p == 1) ? iw : hw;
    float2 v;
    v.x = tf32r(W[(size_t)n * DD + k]);
    v.y = tf32r(W[(size_t)n * DD + k + 4]);
    *(float2*)&g_Wf[(size_t)idx * 2] = v;
}

// ---------------------------------------------------------------------------
// scan phases (unchanged; near HBM roofline)
// ---------------------------------------------------------------------------
__global__ void scan_phaseA_kernel()
{
    int idx = blockIdx.x * blockDim.x + threadIdx.x;
    int h   = idx % HH;
    int rem = idx / HH;
    int c   = rem % NC;
    int b   = rem / NC;

    size_t base = ((size_t)b * TT + (size_t)c * CHUNK) * HH + h;
    float Ap = 1.0f, Bc = 0.0f;
    #pragma unroll 4
    for (int t = 0; t < CHUNK; t++) {
        float a  = g_A [base + (size_t)t * HH];
        float bb = g_Bv[base + (size_t)t * HH];
        Bc = fmaf(a, Bc, bb);
        Ap = Ap * a;
    }
    g_aggA[idx] = Ap;
    g_aggB[idx] = Bc;
}

__global__ void scan_phaseB_kernel(const float* __restrict__ h0)
{
    int idx = blockIdx.x * blockDim.x + threadIdx.x;
    int h = idx % HH;
    int b = idx / HH;

    float hp = h0[(size_t)b * HH + h];
    #pragma unroll
    for (int c = 0; c < NC; c++) {
        size_t ai = ((size_t)b * NC + c) * HH + h;
        g_pref[ai] = hp;
        hp = fmaf(g_aggA[ai], hp, g_aggB[ai]);
    }
}

__global__ void scan_phaseC_kernel(float* __restrict__ out)
{
    int idx = blockIdx.x * blockDim.x + threadIdx.x;
    int h   = idx % HH;
    int rem = idx / HH;
    int c   = rem % NC;
    int b   = rem / NC;

    size_t base = ((size_t)b * TT + (size_t)c * CHUNK) * HH + h;
    float hcur = g_pref[idx];
    #pragma unroll 4
    for (int t = 0; t < CHUNK; t++) {
        size_t o = base + (size_t)t * HH;
        hcur = fmaf(g_A[o], hcur, g_Bv[o]);
        out[o] = hcur;
    }
}

// ---------------------------------------------------------------------------
extern "C" void kernel_launch(void* const* d_in, const int* in_sizes, int n_in,
                              void* d_out, int out_size)
{
    const float* x  = (const float*)d_in[0];
    const float* h0 = (const float*)d_in[1];
    const float* fw = (const float*)d_in[2];
    const float* fb = (const float*)d_in[3];
    const float* iw = (const float*)d_in[4];
    const float* ib = (const float*)d_in[5];
    const float* hw = (const float*)d_in[6];
    const float* hb = (const float*)d_in[7];
    float* out = (float*)d_out;

    cudaFuncSetAttribute(gates_gemm_fm,
                         cudaFuncAttributeMaxDynamicSharedMemorySize, SMEM_BYTES);

    // prep: fragment-major tf32 operands
    permute_x_kernel<<<(NMB * NKB * 32) / 256, 256>>>(x);
    permute_w_kernel<<<(3 * NNB * NKB * 32) / 256, 256>>>(fw, iw, hw);

    // triple GEMM + gate epilogue
    dim3 ggrid(HH / GBN, MM / GBM);   // (12, 256)
    gates_gemm_fm<<<ggrid, 256, SMEM_BYTES>>>(fb, ib, hb);

    // scans
    scan_phaseA_kernel<<<(BATCH * NC * HH) / 256, 256>>>();
    scan_phaseB_kernel<<<(BATCH * HH) / 256, 256>>>(h0);
    scan_phaseC_kernel<<<(BATCH * NC * HH) / 256, 256>>>(out);
}

// round 13
// speedup vs baseline: 1.0490x; 1.0490x over previous
#include <cuda_runtime.h>
#include <math.h>
#include <stdint.h>

// Problem constants
#define BATCH 8
#define TT    4096
#define DD    768
#define HH    768
#define MM    (BATCH * TT)      // 32768 rows
#define CHUNK 64                // = GBM: one GEMM CTA = one scan chunk
#define NC    (TT / CHUNK)      // 64 chunks

#define NKB   (DD / 8)          // 96 k8 blocks
#define NMB   (MM / 16)         // 2048 m16 blocks
#define NNB   (HH / 8)          // 96 n8 blocks

// Scratch (static device globals)
__device__ float g_A [(size_t)MM * HH];
__device__ float g_Bv[(size_t)MM * HH];
__device__ float g_Xf[(size_t)MM * DD];        // fragment-major tf32 x
__device__ float g_Wf[(size_t)3 * HH * DD];    // fragment-major tf32 weights
__device__ float g_aggA[BATCH * NC * HH];
__device__ float g_aggB[BATCH * NC * HH];
__device__ float g_pref[BATCH * NC * HH];

// ---------------------------------------------------------------------------
// GEMM: BM=64 x BN=64 x BK=32, 256 threads, 8 warps (2m x 4n), warp tile
// 32x16 = 2(m16) x 2(n8) mma tiles x 3 projections. 3-stage cp.async on
// fragment-major operands. Epilogue ALSO computes the per-chunk (CHUNK=64)
// scan aggregate in-register/smem, eliminating the phaseA kernel.
// ---------------------------------------------------------------------------
#define GBM 64
#define GBN 64
#define STAGES 3
#define N_ITERS (DD / 32)            // 24 iterations of 4 k8-blocks
#define A_STG_FLOATS 2048            // 4 m16 x 4 k8 x 128
#define B_STG_FLOATS 2048            // 8 n8  x 4 k8 x 64, per projection
#define STAGE_FLOATS (A_STG_FLOATS + 3 * B_STG_FLOATS)   // 8192 (32 KB)
#define SMEM_BYTES (STAGES * STAGE_FLOATS * 4)           // 98304
#define TPAD 68                       // transpose pad (conflict-free writes)

__device__ __forceinline__ float tf32r(float f) {
    uint32_t u;
    asm("cvt.rna.tf32.f32 %0, %1;" : "=r"(u) : "f"(f));
    return __uint_as_float(u);
}
__device__ __forceinline__ uint32_t smem_u32(const void* p) {
    uint32_t a;
    asm("{ .reg .u64 t; cvta.to.shared.u64 t, %1; cvt.u32.u64 %0, t; }" : "=r"(a) : "l"(p));
    return a;
}
__device__ __forceinline__ void cp16(uint32_t d, const float* g) {
    uint64_t ga;
    asm("cvta.to.global.u64 %0, %1;" : "=l"(ga) : "l"(g));
    asm volatile("cp.async.cg.shared.global [%0], [%1], 16;" :: "r"(d), "l"(ga) : "memory");
}
__device__ __forceinline__ void mma_tf32(float& c0, float& c1, float& c2, float& c3,
                                         uint32_t a0, uint32_t a1, uint32_t a2, uint32_t a3,
                                         uint32_t b0, uint32_t b1) {
    asm volatile(
        "mma.sync.aligned.m16n8k8.row.col.f32.tf32.tf32.f32 "
        "{%0,%1,%2,%3}, {%4,%5,%6,%7}, {%8,%9}, {%0,%1,%2,%3};\n"
        : "+f"(c0), "+f"(c1), "+f"(c2), "+f"(c3)
        : "r"(a0), "r"(a1), "r"(a2), "r"(a3), "r"(b0), "r"(b1));
}

extern __shared__ float smf[];

__global__ __launch_bounds__(256, 2)
void gates_gemm_fm(const float* __restrict__ fb, const float* __restrict__ ib,
                   const float* __restrict__ hb)
{
    const int tid = threadIdx.x;
    const int L   = tid & 31;
    const int w   = tid >> 5;
    const int wm  = w >> 2;          // 0..1 -> 32-row band
    const int wn  = w & 3;           // 0..3 -> 16-col band
    const int m0b = blockIdx.y * GBM;
    const int n0b = blockIdx.x * GBN;
    const int mb0 = blockIdx.y * 4;  // first m16 block
    const int nb0 = blockIdx.x * 8;  // first n8 block

    const uint32_t s_u = smem_u32(smf);

    float cf[2][2][4] = {}, ci[2][2][4] = {}, ch[2][2][4] = {};

#define ISSUE_LOAD(ST, IT)                                                     \
    {                                                                          \
        uint32_t sb = s_u + (uint32_t)(ST) * (STAGE_FLOATS * 4);               \
        const int kb0 = (IT) * 4;                                              \
        _Pragma("unroll")                                                      \
        for (int i = 0; i < 2; i++) {                                          \
            int chunk = tid + i * 256;           /* 0..511, 16B each */        \
            int seg = chunk >> 7, within = chunk & 127;                        \
            const float* gs = g_Xf + (((size_t)(mb0 + seg) * NKB + kb0) * 128) \
                              + within * 4;                                    \
            cp16(sb + chunk * 16, gs);                                         \
        }                                                                      \
        _Pragma("unroll")                                                      \
        for (int p = 0; p < 3; p++) {                                          \
            uint32_t bb = sb + (A_STG_FLOATS + p * B_STG_FLOATS) * 4;          \
            _Pragma("unroll")                                                  \
            for (int i = 0; i < 2; i++) {                                      \
                int chunk = tid + i * 256;                                     \
                int seg = chunk >> 6, within = chunk & 63;                     \
                const float* gs = g_Wf +                                       \
                    (((size_t)(p * NNB + nb0 + seg) * NKB + kb0) * 64)         \
                    + within * 4;                                              \
                cp16(bb + chunk * 16, gs);                                     \
            }                                                                  \
        }                                                                      \
    }

#define COMPUTE(ST)                                                            \
    {                                                                          \
        const float* sA  = smf + (ST) * STAGE_FLOATS;                          \
        const float* sB0 = sA + A_STG_FLOATS;                                  \
        const float* sB1 = sB0 + B_STG_FLOATS;                                 \
        const float* sB2 = sB1 + B_STG_FLOATS;                                 \
        _Pragma("unroll")                                                      \
        for (int kb4 = 0; kb4 < 4; kb4++) {                                    \
            uint32_t A[2][4];                                                  \
            _Pragma("unroll")                                                  \
            for (int mt = 0; mt < 2; mt++) {                                   \
                int mb4 = wm * 2 + mt;                                         \
                float4 av = *(const float4*)&sA[(mb4 * 4 + kb4) * 128 + L * 4];\
                A[mt][0] = __float_as_uint(av.x);                              \
                A[mt][1] = __float_as_uint(av.y);                              \
                A[mt][2] = __float_as_uint(av.z);                              \
                A[mt][3] = __float_as_uint(av.w);                              \
            }                                                                  \
            _Pragma("unroll")                                                  \
            for (int nt = 0; nt < 2; nt++) {                                   \
                int off = ((wn * 2 + nt) * 4 + kb4) * 64 + L * 2;              \
                float2 vf = *(const float2*)&sB0[off];                         \
                float2 vi = *(const float2*)&sB1[off];                         \
                float2 vh = *(const float2*)&sB2[off];                         \
                _Pragma("unroll")                                              \
                for (int mt = 0; mt < 2; mt++) {                               \
                    mma_tf32(cf[mt][nt][0], cf[mt][nt][1], cf[mt][nt][2], cf[mt][nt][3], \
                             A[mt][0], A[mt][1], A[mt][2], A[mt][3],           \
                             __float_as_uint(vf.x), __float_as_uint(vf.y));    \
                    mma_tf32(ci[mt][nt][0], ci[mt][nt][1], ci[mt][nt][2], ci[mt][nt][3], \
                             A[mt][0], A[mt][1], A[mt][2], A[mt][3],           \
                             __float_as_uint(vi.x), __float_as_uint(vi.y));    \
                    mma_tf32(ch[mt][nt][0], ch[mt][nt][1], ch[mt][nt][2], ch[mt][nt][3], \
                             A[mt][0], A[mt][1], A[mt][2], A[mt][3],           \
                             __float_as_uint(vh.x), __float_as_uint(vh.y));    \
                }                                                              \
            }                                                                  \
        }                                                                      \
    }

    // ---- prologue ----
    ISSUE_LOAD(0, 0);
    asm volatile("cp.async.commit_group;" ::: "memory");
    ISSUE_LOAD(1, 1);
    asm volatile("cp.async.commit_group;" ::: "memory");

    // ---- mainloop ----
    int st = 0, nst = 2;
    for (int it = 0; it < N_ITERS; it++) {
        asm volatile("cp.async.wait_group %0;" :: "n"(STAGES - 2) : "memory");
        __syncthreads();
        int nk = it + STAGES - 1;
        if (nk < N_ITERS) { ISSUE_LOAD(nst, nk); }
        asm volatile("cp.async.commit_group;" ::: "memory");
        COMPUTE(st);
        st = (st + 1 == STAGES) ? 0 : st + 1;
        nst = (nst + 1 == STAGES) ? 0 : nst + 1;
    }

    // ---- epilogue 1: gates -> (a, b); write global + smem transpose ----
    __syncthreads();                       // stages dead; reuse smem
    float* sa = smf;                       // [64][TPAD]
    float* sbv = smf + 64 * TPAD;          // [64][TPAD]

    #pragma unroll
    for (int mt = 0; mt < 2; mt++) {
        #pragma unroll
        for (int nt = 0; nt < 2; nt++) {
            int rl = wm * 32 + mt * 16 + (L >> 2);
            int cl = wn * 16 + nt * 8 + 2 * (L & 3);
            #pragma unroll
            for (int e = 0; e < 4; e++) {
                int ml = rl + ((e >> 1) ? 8 : 0);
                int hl = cl + (e & 1);
                int h  = n0b + hl;
                float fv = 1.0f / (1.0f + __expf(-(cf[mt][nt][e] + fb[h])));
                float iv = 1.0f / (1.0f + __expf(-(ci[mt][nt][e] + ib[h])));
                float ht = ch[mt][nt][e] + hb[h];
                float inv_den = 1.0f / (fv + iv + 1e-8f);
                float av = fv * inv_den;
                float bv = iv * inv_den * ht;
                size_t o = (size_t)(m0b + ml) * HH + h;
                g_A [o] = av;
                g_Bv[o] = bv;
                sa [hl * TPAD + ml] = av;
                sbv[hl * TPAD + ml] = bv;
            }
        }
    }
    __syncthreads();

    // ---- epilogue 2: chunk aggregate (CHUNK=64 == CTA rows) ----
    {
        const int hc = tid >> 2;          // 0..63 column
        const int q  = tid & 3;           // t quarter
        const float* pa = &sa [hc * TPAD + q * 16];
        const float* pb = &sbv[hc * TPAD + q * 16];
        float Ar = 1.0f, Br = 0.0f;
        #pragma unroll
        for (int j = 0; j < 16; j++) {
            float a = pa[j], bb2 = pb[j];
            Br = fmaf(a, Br, bb2);
            Ar = Ar * a;
        }
        // ordered combine across q (within lane quad)
        {
            float A2 = __shfl_xor_sync(0xFFFFFFFFu, Ar, 1);
            float B2 = __shfl_xor_sync(0xFFFFFFFFu, Br, 1);
            if (q & 1) { Br = fmaf(Ar, B2, Br); }   // partner first, self second
            else       { Br = fmaf(A2, Br, B2); }   // self first, partner second
            Ar = Ar * A2;
        }
        {
            float A2 = __shfl_xor_sync(0xFFFFFFFFu, Ar, 2);
            float B2 = __shfl_xor_sync(0xFFFFFFFFu, Br, 2);
            if (q & 2) { Br = fmaf(Ar, B2, Br); }
            else       { Br = fmaf(A2, Br, B2); }
            Ar = Ar * A2;
        }
        if (q == 0) {
            int b = m0b >> 12;                 // /4096
            int c = (m0b & 4095) >> 6;         // /64 within batch
            size_t ai = ((size_t)b * NC + c) * HH + n0b + hc;
            g_aggA[ai] = Ar;
            g_aggB[ai] = Br;
        }
    }
#undef ISSUE_LOAD
#undef COMPUTE
}

// ---------------------------------------------------------------------------
// Prep: permute + tf32-round operands into fragment-major scratch.
// ---------------------------------------------------------------------------
__global__ void permute_x_kernel(const float* __restrict__ x)
{
    int idx = blockIdx.x * blockDim.x + threadIdx.x;   // < NMB*NKB*32
    int L  = idx & 31;
    int kb = (idx >> 5) % NKB;
    int mb = (idx >> 5) / NKB;
    int r = mb * 16 + (L >> 2);
    int c = kb * 8 + (L & 3);
    float4 v;
    v.x = tf32r(x[(size_t)r * DD + c]);
    v.y = tf32r(x[(size_t)(r + 8) * DD + c]);
    v.z = tf32r(x[(size_t)r * DD + c + 4]);
    v.w = tf32r(x[(size_t)(r + 8) * DD + c + 4]);
    *(float4*)&g_Xf[(size_t)idx * 4] = v;
}

__global__ void permute_w_kernel(const float* __restrict__ fw,
                                 const float* __restrict__ iw,
                                 const float* __restrict__ hw)
{
    int idx = blockIdx.x * blockDim.x + threadIdx.x;   // < 3*NNB*NKB*32
    int L  = idx & 31;
    int kb = (idx >> 5) % NKB;
    int nb = ((idx >> 5) / NKB) % NNB;
    int p  = (idx >> 5) / (NKB * NNB);
    int n = nb * 8 + (L >> 2);
    int k = kb * 8 + (L & 3);
    const float* W = (p == 0) ? fw : (p == 1) ? iw : hw;
    float2 v;
    v.x = tf32r(W[(size_t)n * DD + k]);
    v.y = tf32r(W[(size_t)n * DD + k + 4]);
    *(float2*)&g_Wf[(size_t)idx * 2] = v;
}

// ---------------------------------------------------------------------------
// Phase B: serial composition across NC=64 chunks. Tiny.
// ---------------------------------------------------------------------------
__global__ void scan_phaseB_kernel(const float* __restrict__ h0)
{
    int idx = blockIdx.x * blockDim.x + threadIdx.x;   // < BATCH*HH
    int h = idx % HH;
    int b = idx / HH;

    float hp = h0[(size_t)b * HH + h];
    #pragma unroll 8
    for (int c = 0; c < NC; c++) {
        size_t ai = ((size_t)b * NC + c) * HH + h;
        g_pref[ai] = hp;
        hp = fmaf(g_aggA[ai], hp, g_aggB[ai]);
    }
}

// ---------------------------------------------------------------------------
// Phase C: replay each chunk with its prefix, write h_t to out.
// ---------------------------------------------------------------------------
__global__ void scan_phaseC_kernel(float* __restrict__ out)
{
    int idx = blockIdx.x * blockDim.x + threadIdx.x;   // < BATCH*NC*HH
    int h   = idx % HH;
    int rem = idx / HH;
    int c   = rem % NC;
    int b   = rem / NC;

    size_t base = ((size_t)b * TT + (size_t)c * CHUNK) * HH + h;
    float hcur = g_pref[idx];
    #pragma unroll 4
    for (int t = 0; t < CHUNK; t++) {
        size_t o = base + (size_t)t * HH;
        hcur = fmaf(g_A[o], hcur, g_Bv[o]);
        out[o] = hcur;
    }
}

// ---------------------------------------------------------------------------
extern "C" void kernel_launch(void* const* d_in, const int* in_sizes, int n_in,
                              void* d_out, int out_size)
{
    const float* x  = (const float*)d_in[0];
    const float* h0 = (const float*)d_in[1];
    const float* fw = (const float*)d_in[2];
    const float* fb = (const float*)d_in[3];
    const float* iw = (const float*)d_in[4];
    const float* ib = (const float*)d_in[5];
    const float* hw = (const float*)d_in[6];
    const float* hb = (const float*)d_in[7];
    float* out = (float*)d_out;

    cudaFuncSetAttribute(gates_gemm_fm,
                         cudaFuncAttributeMaxDynamicSharedMemorySize, SMEM_BYTES);

    // prep: fragment-major tf32 operands
    permute_x_kernel<<<(NMB * NKB * 32) / 256, 256>>>(x);
    permute_w_kernel<<<(3 * NNB * NKB * 32) / 256, 256>>>(fw, iw, hw);

    // triple GEMM + gate epilogue + fused chunk aggregates (phase A)
    dim3 ggrid(HH / GBN, MM / GBM);   // (12, 512)
    gates_gemm_fm<<<ggrid, 256, SMEM_BYTES>>>(fb, ib, hb);

    // scans
    scan_phaseB_kernel<<<(BATCH * HH) / 256, 256>>>(h0);
    scan_phaseC_kernel<<<(BATCH * NC * HH) / 256, 256>>>(out);
}

// round 16
// speedup vs baseline: 1.0878x; 1.0370x over previous
#include <cuda_runtime.h>
#include <math.h>
#include <stdint.h>

// Problem constants
#define BATCH 8
#define TT    4096
#define DD    768
#define HH    768
#define MM    (BATCH * TT)      // 32768 rows
#define CHUNK 64                // = GBM: one GEMM CTA = one scan chunk
#define NC    (TT / CHUNK)      // 64 chunks

#define NKB   (DD / 8)          // 96 k8 blocks
#define NMB   (MM / 16)         // 2048 m16 blocks
#define NNB   (HH / 8)          // 96 n8 blocks

// Scratch (static device globals)
__device__ float g_A [(size_t)MM * HH];
__device__ float g_Bv[(size_t)MM * HH];
__device__ float g_Xf[(size_t)MM * DD];        // fragment-major tf32 x
__device__ float g_Wf[(size_t)3 * HH * DD];    // fragment-major tf32 weights
__device__ float g_aggA[BATCH * NC * HH];
__device__ float g_aggB[BATCH * NC * HH];
__device__ float g_pref[BATCH * NC * HH];

// ---------------------------------------------------------------------------
// GEMM: BM=64 x BN=64 x BK=32, 256 threads, 8 warps (2m x 4n), warp tile
// 32x16 = 2(m16) x 2(n8) mma tiles x 3 projections. 3-stage cp.async on
// fragment-major operands. Epilogue computes the per-chunk (CHUNK=64)
// scan aggregate (fused phase A).
// ---------------------------------------------------------------------------
#define GBM 64
#define GBN 64
#define STAGES 3
#define N_ITERS (DD / 32)            // 24 iterations of 4 k8-blocks
#define A_STG_FLOATS 2048            // 4 m16 x 4 k8 x 128
#define B_STG_FLOATS 2048            // 8 n8  x 4 k8 x 64, per projection
#define STAGE_FLOATS (A_STG_FLOATS + 3 * B_STG_FLOATS)   // 8192 (32 KB)
#define SMEM_BYTES (STAGES * STAGE_FLOATS * 4)           // 98304
#define TPAD 68                       // transpose pad (conflict-free writes)

__device__ __forceinline__ float tf32r(float f) {
    uint32_t u;
    asm("cvt.rna.tf32.f32 %0, %1;" : "=r"(u) : "f"(f));
    return __uint_as_float(u);
}
__device__ __forceinline__ uint32_t smem_u32(const void* p) {
    uint32_t a;
    asm("{ .reg .u64 t; cvta.to.shared.u64 t, %1; cvt.u32.u64 %0, t; }" : "=r"(a) : "l"(p));
    return a;
}
__device__ __forceinline__ void cp16(uint32_t d, const float* g) {
    uint64_t ga;
    asm("cvta.to.global.u64 %0, %1;" : "=l"(ga) : "l"(g));
    asm volatile("cp.async.cg.shared.global [%0], [%1], 16;" :: "r"(d), "l"(ga) : "memory");
}
__device__ __forceinline__ void mma_tf32(float& c0, float& c1, float& c2, float& c3,
                                         uint32_t a0, uint32_t a1, uint32_t a2, uint32_t a3,
                                         uint32_t b0, uint32_t b1) {
    asm volatile(
        "mma.sync.aligned.m16n8k8.row.col.f32.tf32.tf32.f32 "
        "{%0,%1,%2,%3}, {%4,%5,%6,%7}, {%8,%9}, {%0,%1,%2,%3};\n"
        : "+f"(c0), "+f"(c1), "+f"(c2), "+f"(c3)
        : "r"(a0), "r"(a1), "r"(a2), "r"(a3), "r"(b0), "r"(b1));
}

extern __shared__ float smf[];

__global__ __launch_bounds__(256, 2)
void gates_gemm_fm(const float* __restrict__ fb, const float* __restrict__ ib,
                   const float* __restrict__ hb)
{
    const int tid = threadIdx.x;
    const int L   = tid & 31;
    const int w   = tid >> 5;
    const int wm  = w >> 2;          // 0..1 -> 32-row band
    const int wn  = w & 3;           // 0..3 -> 16-col band
    const int m0b = blockIdx.y * GBM;
    const int n0b = blockIdx.x * GBN;
    const int mb0 = blockIdx.y * 4;  // first m16 block
    const int nb0 = blockIdx.x * 8;  // first n8 block

    const uint32_t s_u = smem_u32(smf);

    float cf[2][2][4] = {}, ci[2][2][4] = {}, ch[2][2][4] = {};

#define ISSUE_LOAD(ST, IT)                                                     \
    {                                                                          \
        uint32_t sb = s_u + (uint32_t)(ST) * (STAGE_FLOATS * 4);               \
        const int kb0 = (IT) * 4;                                              \
        _Pragma("unroll")                                                      \
        for (int i = 0; i < 2; i++) {                                          \
            int chunk = tid + i * 256;           /* 0..511, 16B each */        \
            int seg = chunk >> 7, within = chunk & 127;                        \
            const float* gs = g_Xf + (((size_t)(mb0 + seg) * NKB + kb0) * 128) \
                              + within * 4;                                    \
            cp16(sb + chunk * 16, gs);                                         \
        }                                                                      \
        _Pragma("unroll")                                                      \
        for (int p = 0; p < 3; p++) {                                          \
            uint32_t bb = sb + (A_STG_FLOATS + p * B_STG_FLOATS) * 4;          \
            _Pragma("unroll")                                                  \
            for (int i = 0; i < 2; i++) {                                      \
                int chunk = tid + i * 256;                                     \
                int seg = chunk >> 6, within = chunk & 63;                     \
                const float* gs = g_Wf +                                       \
                    (((size_t)(p * NNB + nb0 + seg) * NKB + kb0) * 64)         \
                    + within * 4;                                              \
                cp16(bb + chunk * 16, gs);                                     \
            }                                                                  \
        }                                                                      \
    }

#define COMPUTE(ST)                                                            \
    {                                                                          \
        const float* sA  = smf + (ST) * STAGE_FLOATS;                          \
        const float* sB0 = sA + A_STG_FLOATS;                                  \
        const float* sB1 = sB0 + B_STG_FLOATS;                                 \
        const float* sB2 = sB1 + B_STG_FLOATS;                                 \
        _Pragma("unroll")                                                      \
        for (int kb4 = 0; kb4 < 4; kb4++) {                                    \
            uint32_t A[2][4];                                                  \
            _Pragma("unroll")                                                  \
            for (int mt = 0; mt < 2; mt++) {                                   \
                int mb4 = wm * 2 + mt;                                         \
                float4 av = *(const float4*)&sA[(mb4 * 4 + kb4) * 128 + L * 4];\
                A[mt][0] = __float_as_uint(av.x);                              \
                A[mt][1] = __float_as_uint(av.y);                              \
                A[mt][2] = __float_as_uint(av.z);                              \
                A[mt][3] = __float_as_uint(av.w);                              \
            }                                                                  \
            _Pragma("unroll")                                                  \
            for (int nt = 0; nt < 2; nt++) {                                   \
                int off = ((wn * 2 + nt) * 4 + kb4) * 64 + L * 2;              \
                float2 vf = *(const float2*)&sB0[off];                         \
                float2 vi = *(const float2*)&sB1[off];                         \
                float2 vh = *(const float2*)&sB2[off];                         \
                _Pragma("unroll")                                              \
                for (int mt = 0; mt < 2; mt++) {                               \
                    mma_tf32(cf[mt][nt][0], cf[mt][nt][1], cf[mt][nt][2], cf[mt][nt][3], \
                             A[mt][0], A[mt][1], A[mt][2], A[mt][3],           \
                             __float_as_uint(vf.x), __float_as_uint(vf.y));    \
                    mma_tf32(ci[mt][nt][0], ci[mt][nt][1], ci[mt][nt][2], ci[mt][nt][3], \
                             A[mt][0], A[mt][1], A[mt][2], A[mt][3],           \
                             __float_as_uint(vi.x), __float_as_uint(vi.y));    \
                    mma_tf32(ch[mt][nt][0], ch[mt][nt][1], ch[mt][nt][2], ch[mt][nt][3], \
                             A[mt][0], A[mt][1], A[mt][2], A[mt][3],           \
                             __float_as_uint(vh.x), __float_as_uint(vh.y));    \
                }                                                              \
            }                                                                  \
        }                                                                      \
    }

    // ---- prologue ----
    ISSUE_LOAD(0, 0);
    asm volatile("cp.async.commit_group;" ::: "memory");
    ISSUE_LOAD(1, 1);
    asm volatile("cp.async.commit_group;" ::: "memory");

    // ---- mainloop ----
    int st = 0, nst = 2;
    for (int it = 0; it < N_ITERS; it++) {
        asm volatile("cp.async.wait_group %0;" :: "n"(STAGES - 2) : "memory");
        __syncthreads();
        int nk = it + STAGES - 1;
        if (nk < N_ITERS) { ISSUE_LOAD(nst, nk); }
        asm volatile("cp.async.commit_group;" ::: "memory");
        COMPUTE(st);
        st = (st + 1 == STAGES) ? 0 : st + 1;
        nst = (nst + 1 == STAGES) ? 0 : nst + 1;
    }

    // ---- epilogue 1: gates -> (a, b); write global + smem transpose ----
    __syncthreads();                       // stages dead; reuse smem
    float* sa = smf;                       // [64][TPAD]
    float* sbv = smf + 64 * TPAD;          // [64][TPAD]

    #pragma unroll
    for (int mt = 0; mt < 2; mt++) {
        #pragma unroll
        for (int nt = 0; nt < 2; nt++) {
            int rl = wm * 32 + mt * 16 + (L >> 2);
            int cl = wn * 16 + nt * 8 + 2 * (L & 3);
            #pragma unroll
            for (int e = 0; e < 4; e++) {
                int ml = rl + ((e >> 1) ? 8 : 0);
                int hl = cl + (e & 1);
                int h  = n0b + hl;
                float fv = 1.0f / (1.0f + __expf(-(cf[mt][nt][e] + fb[h])));
                float iv = 1.0f / (1.0f + __expf(-(ci[mt][nt][e] + ib[h])));
                float ht = ch[mt][nt][e] + hb[h];
                float inv_den = 1.0f / (fv + iv + 1e-8f);
                float av = fv * inv_den;
                float bv = iv * inv_den * ht;
                size_t o = (size_t)(m0b + ml) * HH + h;
                g_A [o] = av;
                g_Bv[o] = bv;
                sa [hl * TPAD + ml] = av;
                sbv[hl * TPAD + ml] = bv;
            }
        }
    }
    __syncthreads();

    // ---- epilogue 2: chunk aggregate (CHUNK=64 == CTA rows) ----
    {
        const int hc = tid >> 2;          // 0..63 column
        const int q  = tid & 3;           // t quarter
        const float* pa = &sa [hc * TPAD + q * 16];
        const float* pb = &sbv[hc * TPAD + q * 16];
        float Ar = 1.0f, Br = 0.0f;
        #pragma unroll
        for (int j = 0; j < 16; j++) {
            float a = pa[j], bb2 = pb[j];
            Br = fmaf(a, Br, bb2);
            Ar = Ar * a;
        }
        {
            float A2 = __shfl_xor_sync(0xFFFFFFFFu, Ar, 1);
            float B2 = __shfl_xor_sync(0xFFFFFFFFu, Br, 1);
            if (q & 1) { Br = fmaf(Ar, B2, Br); }
            else       { Br = fmaf(A2, Br, B2); }
            Ar = Ar * A2;
        }
        {
            float A2 = __shfl_xor_sync(0xFFFFFFFFu, Ar, 2);
            float B2 = __shfl_xor_sync(0xFFFFFFFFu, Br, 2);
            if (q & 2) { Br = fmaf(Ar, B2, Br); }
            else       { Br = fmaf(A2, Br, B2); }
            Ar = Ar * A2;
        }
        if (q == 0) {
            int b = m0b >> 12;                 // /4096
            int c = (m0b & 4095) >> 6;         // /64 within batch
            size_t ai = ((size_t)b * NC + c) * HH + n0b + hc;
            g_aggA[ai] = Ar;
            g_aggB[ai] = Br;
        }
    }
#undef ISSUE_LOAD
#undef COMPUTE
}

// ---------------------------------------------------------------------------
// Prep: permute + tf32-round x into fragment-major scratch, coalesced via smem.
// Block = one m16 block x half the k range (384 cols). smem 16x388 floats.
// ---------------------------------------------------------------------------
#define PKH 384                      // k columns per block
#define PKB (PKH / 8)                // 48 k8 blocks per block
#define PPAD 388

__global__ __launch_bounds__(256)
void permute_x_smem(const float* __restrict__ x)
{
    __shared__ float sx[16 * PPAD];
    const int mb  = blockIdx.x >> 1;
    const int kh  = blockIdx.x & 1;           // which k half
    const float* xb = x + (size_t)mb * 16 * DD + kh * PKH;

    // coalesced load: 16 rows x 384 cols = 1536 float4
    for (int i = threadIdx.x; i < 16 * (PKH / 4); i += 256) {
        int r = i / (PKH / 4), c4 = i % (PKH / 4);
        float4 v = *(const float4*)&xb[(size_t)r * DD + c4 * 4];
        v.x = tf32r(v.x); v.y = tf32r(v.y); v.z = tf32r(v.z); v.w = tf32r(v.w);
        *(float4*)&sx[r * PPAD + c4 * 4] = v;
    }
    __syncthreads();

    // fragment-major write: PKB*32 = 1536 float4, coalesced
    for (int i = threadIdx.x; i < PKB * 32; i += 256) {
        int kb = i >> 5, L = i & 31;
        int r = L >> 2, c = kb * 8 + (L & 3);
        float4 v;
        v.x = sx[r * PPAD + c];
        v.y = sx[(r + 8) * PPAD + c];
        v.z = sx[r * PPAD + c + 4];
        v.w = sx[(r + 8) * PPAD + c + 4];
        *(float4*)&g_Xf[((size_t)mb * NKB + kh * PKB + kb) * 128 + L * 4] = v;
    }
}

__global__ void permute_w_kernel(const float* __restrict__ fw,
                                 const float* __restrict__ iw,
                                 const float* __restrict__ hw)
{
    int idx = blockIdx.x * blockDim.x + threadIdx.x;   // < 3*NNB*NKB*32
    int L  = idx & 31;
    int kb = (idx >> 5) % NKB;
    int nb = ((idx >> 5) / NKB) % NNB;
    int p  = (idx >> 5) / (NKB * NNB);
    int n = nb * 8 + (L >> 2);
    int k = kb * 8 + (L & 3);
    const float* W = (p == 0) ? fw : (p == 1) ? iw : hw;
    float2 v;
    v.x = tf32r(W[(size_t)n * DD + k]);
    v.y = tf32r(W[(size_t)n * DD + k + 4]);
    *(float2*)&g_Wf[(size_t)idx * 2] = v;
}

// ---------------------------------------------------------------------------
// Phase B: warp-parallel Kogge-Stone scan over the NC=64 chunk transforms.
// One warp per (b,h) lane; thread t composes chunks {2t, 2t+1}.
// ---------------------------------------------------------------------------
__global__ __launch_bounds__(256)
void scan_phaseB_warp(const float* __restrict__ h0)
{
    int gw = (blockIdx.x * blockDim.x + threadIdx.x) >> 5;  // < BATCH*HH
    int t  = threadIdx.x & 31;
    int h = gw % HH;
    int b = gw / HH;

    size_t base = (size_t)b * NC * HH + h;
    size_t i0 = base + (size_t)(2 * t) * HH;
    size_t i1 = i0 + HH;
    float a0 = g_aggA[i0], b0 = g_aggB[i0];
    float a1 = g_aggA[i1], b1 = g_aggB[i1];

    // pair composite (chunk 2t applied first, then 2t+1)
    float Ia = a0 * a1;
    float Ib = fmaf(a1, b0, b1);

    // inclusive Kogge-Stone over pair composites
    #pragma unroll
    for (int d = 1; d < 32; d <<= 1) {
        float pa = __shfl_up_sync(0xFFFFFFFFu, Ia, d);
        float pb = __shfl_up_sync(0xFFFFFFFFu, Ib, d);
        if (t >= d) {
            Ib = fmaf(Ia, pb, Ib);   // later(self) after earlier(partner)
            Ia = Ia * pa;
        }
    }
    // exclusive prefix: composite of chunks [0, 2t)
    float Pa = __shfl_up_sync(0xFFFFFFFFu, Ia, 1);
    float Pb = __shfl_up_sync(0xFFFFFFFFu, Ib, 1);
    if (t == 0) { Pa = 1.0f; Pb = 0.0f; }

    float h0v = h0[(size_t)b * HH + h];
    float he0 = fmaf(Pa, h0v, Pb);       // h entering chunk 2t
    float he1 = fmaf(a0, he0, b0);       // h entering chunk 2t+1
    g_pref[i0] = he0;
    g_pref[i1] = he1;
}

// ---------------------------------------------------------------------------
// Phase C: replay each chunk with its prefix, write h_t to out.
// ---------------------------------------------------------------------------
__global__ void scan_phaseC_kernel(float* __restrict__ out)
{
    int idx = blockIdx.x * blockDim.x + threadIdx.x;   // < BATCH*NC*HH
    int h   = idx % HH;
    int rem = idx / HH;
    int c   = rem % NC;
    int b   = rem / NC;

    size_t base = ((size_t)b * TT + (size_t)c * CHUNK) * HH + h;
    float hcur = g_pref[idx];
    #pragma unroll 4
    for (int t = 0; t < CHUNK; t++) {
        size_t o = base + (size_t)t * HH;
        hcur = fmaf(g_A[o], hcur, g_Bv[o]);
        out[o] = hcur;
    }
}

// ---------------------------------------------------------------------------
extern "C" void kernel_launch(void* const* d_in, const int* in_sizes, int n_in,
                              void* d_out, int out_size)
{
    const float* x  = (const float*)d_in[0];
    const float* h0 = (const float*)d_in[1];
    const float* fw = (const float*)d_in[2];
    const float* fb = (const float*)d_in[3];
    const float* iw = (const float*)d_in[4];
    const float* ib = (const float*)d_in[5];
    const float* hw = (const float*)d_in[6];
    const float* hb = (const float*)d_in[7];
    float* out = (float*)d_out;

    cudaFuncSetAttribute(gates_gemm_fm,
                         cudaFuncAttributeMaxDynamicSharedMemorySize, SMEM_BYTES);

    // prep: fragment-major tf32 operands
    permute_x_smem<<<NMB * 2, 256>>>(x);
    permute_w_kernel<<<(3 * NNB * NKB * 32) / 256, 256>>>(fw, iw, hw);

    // triple GEMM + gate epilogue + fused chunk aggregates (phase A)
    dim3 ggrid(HH / GBN, MM / GBM);   // (12, 512)
    gates_gemm_fm<<<ggrid, 256, SMEM_BYTES>>>(fb, ib, hb);

    // scans
    scan_phaseB_warp<<<(BATCH * HH * 32) / 256, 256>>>(h0);
    scan_phaseC_kernel<<<(BATCH * NC * HH) / 256, 256>>>(out);
}

// round 17
// speedup vs baseline: 1.1041x; 1.0150x over previous
#include <cuda_runtime.h>
#include <math.h>
#include <stdint.h>

// Problem constants
#define BATCH 8
#define TT    4096
#define DD    768
#define HH    768
#define MM    (BATCH * TT)      // 32768 rows
#define CHUNK 64                // = GBM: one GEMM CTA = one scan chunk
#define NC    (TT / CHUNK)      // 64 chunks

#define NKB   (DD / 8)          // 96 k8 blocks
#define NMB   (MM / 16)         // 2048 m16 blocks
#define NNB   (HH / 8)          // 96 n8 blocks

// Scratch (static device globals)
__device__ float g_A [(size_t)MM * HH];
__device__ float g_Bv[(size_t)MM * HH];
__device__ float g_Xf[(size_t)MM * DD];        // fragment-major tf32 x
__device__ float g_Wf[(size_t)3 * HH * DD];    // fragment-major tf32 weights
__device__ float g_aggA[BATCH * HH * NC];      // layout [b][h][c] (coalesced phaseB)
__device__ float g_aggB[BATCH * HH * NC];
__device__ float g_pref[BATCH * NC * HH];      // layout [b][c][h] (phaseC-friendly)

// ---------------------------------------------------------------------------
// GEMM: BM=64 x BN=64 x BK=32, 256 threads, 8 warps (2m x 4n), warp tile
// 32x16 = 2(m16) x 2(n8) mma tiles x 3 projections. 3-stage cp.async on
// fragment-major operands. Epilogue computes gates with cheap algebra
// (2 EX2 + 1 RCP instead of 2 EX2 + 3 div) and the fused phase-A aggregate.
// ---------------------------------------------------------------------------
#define GBM 64
#define GBN 64
#define STAGES 3
#define N_ITERS (DD / 32)            // 24 iterations of 4 k8-blocks
#define A_STG_FLOATS 2048
#define B_STG_FLOATS 2048
#define STAGE_FLOATS (A_STG_FLOATS + 3 * B_STG_FLOATS)   // 8192 (32 KB)
#define SMEM_BYTES (STAGES * STAGE_FLOATS * 4)           // 98304
#define TPAD 68

__device__ __forceinline__ float tf32r(float f) {
    uint32_t u;
    asm("cvt.rna.tf32.f32 %0, %1;" : "=r"(u) : "f"(f));
    return __uint_as_float(u);
}
__device__ __forceinline__ uint32_t smem_u32(const void* p) {
    uint32_t a;
    asm("{ .reg .u64 t; cvta.to.shared.u64 t, %1; cvt.u32.u64 %0, t; }" : "=r"(a) : "l"(p));
    return a;
}
__device__ __forceinline__ void cp16(uint32_t d, const float* g) {
    uint64_t ga;
    asm("cvta.to.global.u64 %0, %1;" : "=l"(ga) : "l"(g));
    asm volatile("cp.async.cg.shared.global [%0], [%1], 16;" :: "r"(d), "l"(ga) : "memory");
}
__device__ __forceinline__ float frcp(float x) {
    float r;
    asm("rcp.approx.f32 %0, %1;" : "=f"(r) : "f"(x));
    return r;
}
__device__ __forceinline__ void mma_tf32(float& c0, float& c1, float& c2, float& c3,
                                         uint32_t a0, uint32_t a1, uint32_t a2, uint32_t a3,
                                         uint32_t b0, uint32_t b1) {
    asm volatile(
        "mma.sync.aligned.m16n8k8.row.col.f32.tf32.tf32.f32 "
        "{%0,%1,%2,%3}, {%4,%5,%6,%7}, {%8,%9}, {%0,%1,%2,%3};\n"
        : "+f"(c0), "+f"(c1), "+f"(c2), "+f"(c3)
        : "r"(a0), "r"(a1), "r"(a2), "r"(a3), "r"(b0), "r"(b1));
}

extern __shared__ float smf[];

__global__ __launch_bounds__(256, 2)
void gates_gemm_fm(const float* __restrict__ fb, const float* __restrict__ ib,
                   const float* __restrict__ hb)
{
    const int tid = threadIdx.x;
    const int L   = tid & 31;
    const int w   = tid >> 5;
    const int wm  = w >> 2;
    const int wn  = w & 3;
    const int m0b = blockIdx.y * GBM;
    const int n0b = blockIdx.x * GBN;
    const int mb0 = blockIdx.y * 4;
    const int nb0 = blockIdx.x * 8;

    const uint32_t s_u = smem_u32(smf);

    float cf[2][2][4] = {}, ci[2][2][4] = {}, ch[2][2][4] = {};

#define ISSUE_LOAD(ST, IT)                                                     \
    {                                                                          \
        uint32_t sb = s_u + (uint32_t)(ST) * (STAGE_FLOATS * 4);               \
        const int kb0 = (IT) * 4;                                              \
        _Pragma("unroll")                                                      \
        for (int i = 0; i < 2; i++) {                                          \
            int chunk = tid + i * 256;                                         \
            int seg = chunk >> 7, within = chunk & 127;                        \
            const float* gs = g_Xf + (((size_t)(mb0 + seg) * NKB + kb0) * 128) \
                              + within * 4;                                    \
            cp16(sb + chunk * 16, gs);                                         \
        }                                                                      \
        _Pragma("unroll")                                                      \
        for (int p = 0; p < 3; p++) {                                          \
            uint32_t bb = sb + (A_STG_FLOATS + p * B_STG_FLOATS) * 4;          \
            _Pragma("unroll")                                                  \
            for (int i = 0; i < 2; i++) {                                      \
                int chunk = tid + i * 256;                                     \
                int seg = chunk >> 6, within = chunk & 63;                     \
                const float* gs = g_Wf +                                       \
                    (((size_t)(p * NNB + nb0 + seg) * NKB + kb0) * 64)         \
                    + within * 4;                                              \
                cp16(bb + chunk * 16, gs);                                     \
            }                                                                  \
        }                                                                      \
    }

#define COMPUTE(ST)                                                            \
    {                                                                          \
        const float* sA  = smf + (ST) * STAGE_FLOATS;                          \
        const float* sB0 = sA + A_STG_FLOATS;                                  \
        const float* sB1 = sB0 + B_STG_FLOATS;                                 \
        const float* sB2 = sB1 + B_STG_FLOATS;                                 \
        _Pragma("unroll")                                                      \
        for (int kb4 = 0; kb4 < 4; kb4++) {                                    \
            uint32_t A[2][4];                                                  \
            _Pragma("unroll")                                                  \
            for (int mt = 0; mt < 2; mt++) {                                   \
                int mb4 = wm * 2 + mt;                                         \
                float4 av = *(const float4*)&sA[(mb4 * 4 + kb4) * 128 + L * 4];\
                A[mt][0] = __float_as_uint(av.x);                              \
                A[mt][1] = __float_as_uint(av.y);                              \
                A[mt][2] = __float_as_uint(av.z);                              \
                A[mt][3] = __float_as_uint(av.w);                              \
            }                                                                  \
            _Pragma("unroll")                                                  \
            for (int nt = 0; nt < 2; nt++) {                                   \
                int off = ((wn * 2 + nt) * 4 + kb4) * 64 + L * 2;              \
                float2 vf = *(const float2*)&sB0[off];                         \
                float2 vi = *(const float2*)&sB1[off];                         \
                float2 vh = *(const float2*)&sB2[off];                         \
                _Pragma("unroll")                                              \
                for (int mt = 0; mt < 2; mt++) {                               \
                    mma_tf32(cf[mt][nt][0], cf[mt][nt][1], cf[mt][nt][2], cf[mt][nt][3], \
                             A[mt][0], A[mt][1], A[mt][2], A[mt][3],           \
                             __float_as_uint(vf.x), __float_as_uint(vf.y));    \
                    mma_tf32(ci[mt][nt][0], ci[mt][nt][1], ci[mt][nt][2], ci[mt][nt][3], \
                             A[mt][0], A[mt][1], A[mt][2], A[mt][3],           \
                             __float_as_uint(vi.x), __float_as_uint(vi.y));    \
                    mma_tf32(ch[mt][nt][0], ch[mt][nt][1], ch[mt][nt][2], ch[mt][nt][3], \
                             A[mt][0], A[mt][1], A[mt][2], A[mt][3],           \
                             __float_as_uint(vh.x), __float_as_uint(vh.y));    \
                }                                                              \
            }                                                                  \
        }                                                                      \
    }

    // ---- prologue ----
    ISSUE_LOAD(0, 0);
    asm volatile("cp.async.commit_group;" ::: "memory");
    ISSUE_LOAD(1, 1);
    asm volatile("cp.async.commit_group;" ::: "memory");

    // ---- mainloop ----
    int st = 0, nst = 2;
    for (int it = 0; it < N_ITERS; it++) {
        asm volatile("cp.async.wait_group %0;" :: "n"(STAGES - 2) : "memory");
        __syncthreads();
        int nk = it + STAGES - 1;
        if (nk < N_ITERS) { ISSUE_LOAD(nst, nk); }
        asm volatile("cp.async.commit_group;" ::: "memory");
        COMPUTE(st);
        st = (st + 1 == STAGES) ? 0 : st + 1;
        nst = (nst + 1 == STAGES) ? 0 : nst + 1;
    }

    // ---- epilogue 1: gates -> (a, b); write global + smem transpose ----
    // a = (1+ei)/D, b = (1+ef)/D * h~, D = (1+ef)+(1+ei)+eps(1+ef)(1+ei)
    // (algebraically identical to f/(f+i+eps) etc.; 2 EX2 + 1 RCP.)
    __syncthreads();                       // stages dead; reuse smem
    float* sa = smf;                       // [64][TPAD]
    float* sbv = smf + 64 * TPAD;          // [64][TPAD]

    #pragma unroll
    for (int mt = 0; mt < 2; mt++) {
        #pragma unroll
        for (int nt = 0; nt < 2; nt++) {
            int rl = wm * 32 + mt * 16 + (L >> 2);
            int cl = wn * 16 + nt * 8 + 2 * (L & 3);
            #pragma unroll
            for (int e = 0; e < 4; e++) {
                int ml = rl + ((e >> 1) ? 8 : 0);
                int hl = cl + (e & 1);
                int h  = n0b + hl;
                float F  = fmaxf(cf[mt][nt][e] + fb[h], -30.0f);
                float I  = fmaxf(ci[mt][nt][e] + ib[h], -30.0f);
                float ht = ch[mt][nt][e] + hb[h];
                float ef = __expf(-F);
                float ei = __expf(-I);
                float opf = 1.0f + ef;
                float opi = 1.0f + ei;
                float Dd = fmaf(1e-8f * opf, opi, opf + opi);
                float rD = frcp(Dd);
                float av = opi * rD;
                float bv = opf * rD * ht;
                size_t o = (size_t)(m0b + ml) * HH + h;
                g_A [o] = av;
                g_Bv[o] = bv;
                sa [hl * TPAD + ml] = av;
                sbv[hl * TPAD + ml] = bv;
            }
        }
    }
    __syncthreads();

    // ---- epilogue 2: chunk aggregate (CHUNK=64 == CTA rows) ----
    {
        const int hc = tid >> 2;          // 0..63 column
        const int q  = tid & 3;           // t quarter
        const float* pa = &sa [hc * TPAD + q * 16];
        const float* pb = &sbv[hc * TPAD + q * 16];
        float Ar = 1.0f, Br = 0.0f;
        #pragma unroll
        for (int j = 0; j < 16; j++) {
            float a = pa[j], bb2 = pb[j];
            Br = fmaf(a, Br, bb2);
            Ar = Ar * a;
        }
        {
            float A2 = __shfl_xor_sync(0xFFFFFFFFu, Ar, 1);
            float B2 = __shfl_xor_sync(0xFFFFFFFFu, Br, 1);
            if (q & 1) { Br = fmaf(Ar, B2, Br); }
            else       { Br = fmaf(A2, Br, B2); }
            Ar = Ar * A2;
        }
        {
            float A2 = __shfl_xor_sync(0xFFFFFFFFu, Ar, 2);
            float B2 = __shfl_xor_sync(0xFFFFFFFFu, Br, 2);
            if (q & 2) { Br = fmaf(Ar, B2, Br); }
            else       { Br = fmaf(A2, Br, B2); }
            Ar = Ar * A2;
        }
        if (q == 0) {
            int b = m0b >> 12;                 // /4096
            int c = (m0b & 4095) >> 6;         // /64 within batch
            // layout [b][h][c] for coalesced phaseB reads
            size_t ai = ((size_t)b * HH + n0b + hc) * NC + c;
            g_aggA[ai] = Ar;
            g_aggB[ai] = Br;
        }
    }
#undef ISSUE_LOAD
#undef COMPUTE
}

// ---------------------------------------------------------------------------
// Prep: permute + tf32-round x into fragment-major scratch, coalesced via smem.
// ---------------------------------------------------------------------------
#define PKH 384
#define PKB (PKH / 8)
#define PPAD 388

__global__ __launch_bounds__(256)
void permute_x_smem(const float* __restrict__ x)
{
    __shared__ float sx[16 * PPAD];
    const int mb  = blockIdx.x >> 1;
    const int kh  = blockIdx.x & 1;
    const float* xb = x + (size_t)mb * 16 * DD + kh * PKH;

    for (int i = threadIdx.x; i < 16 * (PKH / 4); i += 256) {
        int r = i / (PKH / 4), c4 = i % (PKH / 4);
        float4 v = *(const float4*)&xb[(size_t)r * DD + c4 * 4];
        v.x = tf32r(v.x); v.y = tf32r(v.y); v.z = tf32r(v.z); v.w = tf32r(v.w);
        *(float4*)&sx[r * PPAD + c4 * 4] = v;
    }
    __syncthreads();

    for (int i = threadIdx.x; i < PKB * 32; i += 256) {
        int kb = i >> 5, L = i & 31;
        int r = L >> 2, c = kb * 8 + (L & 3);
        float4 v;
        v.x = sx[r * PPAD + c];
        v.y = sx[(r + 8) * PPAD + c];
        v.z = sx[r * PPAD + c + 4];
        v.w = sx[(r + 8) * PPAD + c + 4];
        *(float4*)&g_Xf[((size_t)mb * NKB + kh * PKB + kb) * 128 + L * 4] = v;
    }
}

__global__ void permute_w_kernel(const float* __restrict__ fw,
                                 const float* __restrict__ iw,
                                 const float* __restrict__ hw)
{
    int idx = blockIdx.x * blockDim.x + threadIdx.x;
    int L  = idx & 31;
    int kb = (idx >> 5) % NKB;
    int nb = ((idx >> 5) / NKB) % NNB;
    int p  = (idx >> 5) / (NKB * NNB);
    int n = nb * 8 + (L >> 2);
    int k = kb * 8 + (L & 3);
    const float* W = (p == 0) ? fw : (p == 1) ? iw : hw;
    float2 v;
    v.x = tf32r(W[(size_t)n * DD + k]);
    v.y = tf32r(W[(size_t)n * DD + k + 4]);
    *(float2*)&g_Wf[(size_t)idx * 2] = v;
}

// ---------------------------------------------------------------------------
// Phase B: warp-parallel Kogge-Stone scan; aggregates in [b][h][c] layout so
// lane t reads one float2 (chunks 2t, 2t+1) — warp touches 2 cache lines.
// ---------------------------------------------------------------------------
__global__ __launch_bounds__(256)
void scan_phaseB_warp(const float* __restrict__ h0)
{
    int gw = (blockIdx.x * blockDim.x + threadIdx.x) >> 5;  // < BATCH*HH
    int t  = threadIdx.x & 31;
    int h = gw % HH;
    int b = gw / HH;

    size_t lane = ((size_t)b * HH + h) * NC;
    float2 va = *(const float2*)&g_aggA[lane + 2 * t];
    float2 vb = *(const float2*)&g_aggB[lane + 2 * t];
    float a0 = va.x, b0 = vb.x, a1 = va.y, b1 = vb.y;

    float Ia = a0 * a1;
    float Ib = fmaf(a1, b0, b1);

    #pragma unroll
    for (int d = 1; d < 32; d <<= 1) {
        float pa = __shfl_up_sync(0xFFFFFFFFu, Ia, d);
        float pb = __shfl_up_sync(0xFFFFFFFFu, Ib, d);
        if (t >= d) {
            Ib = fmaf(Ia, pb, Ib);
            Ia = Ia * pa;
        }
    }
    float Pa = __shfl_up_sync(0xFFFFFFFFu, Ia, 1);
    float Pb = __shfl_up_sync(0xFFFFFFFFu, Ib, 1);
    if (t == 0) { Pa = 1.0f; Pb = 0.0f; }

    float h0v = h0[(size_t)b * HH + h];
    float he0 = fmaf(Pa, h0v, Pb);
    float he1 = fmaf(a0, he0, b0);
    size_t i0 = ((size_t)b * NC + 2 * t) * HH + h;
    g_pref[i0] = he0;
    g_pref[i0 + HH] = he1;
}

// ---------------------------------------------------------------------------
// Phase C: replay each chunk with its prefix (4 h per thread, float4).
// ---------------------------------------------------------------------------
__global__ void scan_phaseC_kernel(float* __restrict__ out)
{
    int idx = blockIdx.x * blockDim.x + threadIdx.x;   // < BATCH*NC*HH/4
    int h4  = (idx % (HH / 4)) * 4;
    int rem = idx / (HH / 4);
    int c   = rem % NC;
    int b   = rem / NC;

    size_t base = ((size_t)b * TT + (size_t)c * CHUNK) * HH + h4;
    float4 hc = *(const float4*)&g_pref[((size_t)b * NC + c) * HH + h4];
    #pragma unroll 4
    for (int t = 0; t < CHUNK; t++) {
        size_t o = base + (size_t)t * HH;
        float4 a = *(const float4*)&g_A [o];
        float4 bb = *(const float4*)&g_Bv[o];
        hc.x = fmaf(a.x, hc.x, bb.x);
        hc.y = fmaf(a.y, hc.y, bb.y);
        hc.z = fmaf(a.z, hc.z, bb.z);
        hc.w = fmaf(a.w, hc.w, bb.w);
        *(float4*)&out[o] = hc;
    }
}

// ---------------------------------------------------------------------------
extern "C" void kernel_launch(void* const* d_in, const int* in_sizes, int n_in,
                              void* d_out, int out_size)
{
    const float* x  = (const float*)d_in[0];
    const float* h0 = (const float*)d_in[1];
    const float* fw = (const float*)d_in[2];
    const float* fb = (const float*)d_in[3];
    const float* iw = (const float*)d_in[4];
    const float* ib = (const float*)d_in[5];
    const float* hw = (const float*)d_in[6];
    const float* hb = (const float*)d_in[7];
    float* out = (float*)d_out;

    cudaFuncSetAttribute(gates_gemm_fm,
                         cudaFuncAttributeMaxDynamicSharedMemorySize, SMEM_BYTES);

    // prep: fragment-major tf32 operands
    permute_x_smem<<<NMB * 2, 256>>>(x);
    permute_w_kernel<<<(3 * NNB * NKB * 32) / 256, 256>>>(fw, iw, hw);

    // triple GEMM + gate epilogue + fused chunk aggregates (phase A)
    dim3 ggrid(HH / GBN, MM / GBM);   // (12, 512)
    gates_gemm_fm<<<ggrid, 256, SMEM_BYTES>>>(fb, ib, hb);

    // scans
    scan_phaseB_warp<<<(BATCH * HH * 32) / 256, 256>>>(h0);
    scan_phaseC_kernel<<<(BATCH * NC * HH / 4) / 256, 256>>>(out);
}